// round 3
// baseline (speedup 1.0000x reference)
#include <cuda_runtime.h>

#define D_      64
#define K_      16
#define N_      65536
#define P_      2
#define NOISEF  0.1f
#define LOG2PI_F 1.83787706640934534f

#define NBLK    296          // 2 CTAs x 148 SMs, single resident wave
#define TROWS   32           // rows per tile
#define NTILES  (N_ / TROWS) // 2048

__device__ double   g_C[D_ * D_];
__device__ double   g_loss;
__device__ unsigned g_done;

typedef unsigned long long u64;

__device__ __forceinline__ void ffma2(u64& acc, u64 a, u64 b) {
    asm("fma.rn.f32x2 %0, %1, %2, %3;" : "=l"(acc) : "l"(a), "l"(b), "l"(acc));
}
__device__ __forceinline__ u64 dup2(float v) {
    u64 r;
    asm("mov.b64 %0, {%1, %1};" : "=l"(r) : "f"(v));
    return r;
}
__device__ __forceinline__ void cpasync16(unsigned smem, const void* g) {
    asm volatile("cp.async.cg.shared.global [%0], [%1], 16;\n" :: "r"(smem), "l"(g));
}
__device__ __forceinline__ void cp_commit() {
    asm volatile("cp.async.commit_group;\n" ::: "memory");
}
__device__ __forceinline__ void cp_wait0() {
    asm volatile("cp.async.wait_group 0;\n" ::: "memory");
}
__device__ __forceinline__ void cp_wait1() {
    asm volatile("cp.async.wait_group 1;\n" ::: "memory");
}

// ---------------------------------------------------------------------------
// Kernel 1: C = x^T x. Persistent 296 blocks, grid-stride over 2048 tiles of
// 32 rows, cp.async double-buffered. 4 groups of 64 threads; group g handles
// 8 rows of the tile; thread = 8x8 register tile (packed f32x2).
// ---------------------------------------------------------------------------
__global__ __launch_bounds__(256, 2) void k_xtx(const float* __restrict__ x) {
    __shared__ float sx[2][TROWS * 64];

    const int tid = threadIdx.x;
    const int g   = tid >> 6;
    const int t   = tid & 63;
    const int ti  = (t >> 3) << 3;
    const int tj  = (t & 7) << 3;

    u64 acc2[8][4];
#pragma unroll
    for (int u = 0; u < 8; ++u)
#pragma unroll
        for (int v = 0; v < 4; ++v) acc2[u][v] = 0ull;

    const unsigned sbase0 = (unsigned)__cvta_generic_to_shared(&sx[0][0]);
    const unsigned sbase1 = (unsigned)__cvta_generic_to_shared(&sx[1][0]);

    // prefetch first tile
    {
        const float4* g4 = reinterpret_cast<const float4*>(x + (long long)blockIdx.x * TROWS * 64);
        cpasync16(sbase0 + tid * 16, g4 + tid);
        cpasync16(sbase0 + (tid + 256) * 16, g4 + tid + 256);
        cp_commit();
    }

    int buf = 0;
    for (int tile = blockIdx.x; tile < NTILES; tile += NBLK) {
        const int nxt = tile + NBLK;
        if (nxt < NTILES) {
            const unsigned sb = buf ? sbase0 : sbase1;
            const float4* g4 = reinterpret_cast<const float4*>(x + (long long)nxt * TROWS * 64);
            cpasync16(sb + tid * 16, g4 + tid);
            cpasync16(sb + (tid + 256) * 16, g4 + tid + 256);
            cp_commit();
            cp_wait1();
        } else {
            cp_wait0();
        }
        __syncthreads();

        const float* rb = &sx[buf][0] + g * (8 * 64);
#pragma unroll
        for (int rr = 0; rr < 8; ++rr) {
            const float4* xiv = reinterpret_cast<const float4*>(rb + rr * 64 + ti);
            float4 a0 = xiv[0], a1 = xiv[1];
            u64 xi2[8];
            xi2[0] = dup2(a0.x); xi2[1] = dup2(a0.y);
            xi2[2] = dup2(a0.z); xi2[3] = dup2(a0.w);
            xi2[4] = dup2(a1.x); xi2[5] = dup2(a1.y);
            xi2[6] = dup2(a1.z); xi2[7] = dup2(a1.w);
            const u64* xjv = reinterpret_cast<const u64*>(rb + rr * 64 + tj);
            u64 xj2[4];
#pragma unroll
            for (int v = 0; v < 4; ++v) xj2[v] = xjv[v];
#pragma unroll
            for (int u = 0; u < 8; ++u)
#pragma unroll
                for (int v = 0; v < 4; ++v) ffma2(acc2[u][v], xi2[u], xj2[v]);
        }
        __syncthreads();
        buf ^= 1;
    }

    // reduce the 4 groups into sx[0] (4096 floats)
    float* red = &sx[0][0];
    for (int gg = 0; gg < 4; ++gg) {
        if (g == gg) {
#pragma unroll
            for (int u = 0; u < 8; ++u)
#pragma unroll
                for (int v = 0; v < 4; ++v) {
                    float lo = __uint_as_float((unsigned)(acc2[u][v] & 0xffffffffull));
                    float hi = __uint_as_float((unsigned)(acc2[u][v] >> 32));
                    int idx = (ti + u) * 64 + tj + 2 * v;
                    if (gg == 0) { red[idx] = lo; red[idx + 1] = hi; }
                    else         { red[idx] += lo; red[idx + 1] += hi; }
                }
        }
        __syncthreads();
    }

    for (int i = tid; i < 4096; i += 256)
        atomicAdd(&g_C[i], (double)red[i]);
}

// ---------------------------------------------------------------------------
// Kernel 2: one block per (a,p), Woodbury:
//   G = 0.1 I16 + W_r^T W_r ; Y = Cp[:, m:] W_r ; T = W_r^T C_rr W_r
//   b_i = Ginv w_i ; v_i = 0.1(1 + w.b) ; Q_i = Cp_ii - 2 b.Y_i + b^T T b
// Last block to finish writes the output and resets globals (replaces k_out).
// ---------------------------------------------------------------------------
__global__ __launch_bounds__(256) void k_pairs(const float* __restrict__ W,
                                               const int* __restrict__ perms,
                                               float* __restrict__ out) {
    __shared__ float sCraw[D_ * D_];
    __shared__ float sC[D_][D_ + 1];
    __shared__ float sW[D_][K_ + 1];
    __shared__ float sY[D_][K_ + 1];
    __shared__ float sT[K_][K_ + 1];
    __shared__ float sG[K_][2 * K_ + 1];
    __shared__ float sGi[K_][K_ + 1];
    __shared__ float smult[K_];
    __shared__ int   sperm[D_];
    __shared__ float sred[2];
    __shared__ int   slast;

    const int tid = threadIdx.x;
    const int a   = blockIdx.x >> 1;
    const int p   = blockIdx.x & 1;
    const int m   = a + 1;
    const int* perm = perms + (a * P_ + p) * D_;

    if (tid < D_) sperm[tid] = perm[tid];
    for (int i = tid; i < D_ * D_; i += 256)
        sCraw[i] = (float)g_C[i];
    for (int i = tid; i < D_ * K_; i += 256) {
        int row = i >> 4, c = i & 15;
        sW[row][c] = W[perm[row] * K_ + c];
    }
    __syncthreads();

    // permuted C from shared (conflict-light gather)
    for (int i = tid; i < D_ * D_; i += 256) {
        int row = i >> 6, c = i & 63;
        sC[row][c] = sCraw[sperm[row] * D_ + sperm[c]];
    }
    __syncthreads();

    // G (one element per thread) + augmented identity
    {
        int k = tid >> 4, l = tid & 15;
        float s = (k == l) ? NOISEF : 0.f;
        for (int i = m; i < D_; ++i) s += sW[i][k] * sW[i][l];
        sG[k][l] = s;
        sG[k][K_ + l] = (k == l) ? 1.f : 0.f;
    }
    // Y
    {
        int i = tid & 63, kb = (tid >> 6) << 2;
        float y0 = 0.f, y1 = 0.f, y2 = 0.f, y3 = 0.f;
        for (int j = m; j < D_; ++j) {
            float c = sC[i][j];
            y0 += c * sW[j][kb];
            y1 += c * sW[j][kb + 1];
            y2 += c * sW[j][kb + 2];
            y3 += c * sW[j][kb + 3];
        }
        sY[i][kb] = y0; sY[i][kb + 1] = y1; sY[i][kb + 2] = y2; sY[i][kb + 3] = y3;
    }
    __syncthreads();

    // T
    {
        int k = tid >> 4, l = tid & 15;
        float s = 0.f;
        for (int i = m; i < D_; ++i) s += sW[i][k] * sY[i][l];
        sT[k][l] = s;
    }
    // Jordan inversion of 16x16 SPD G
    for (int k = 0; k < K_; ++k) {
        if (tid < K_ && tid != k) smult[tid] = sG[tid][k] / sG[k][k];
        __syncthreads();
        for (int i = tid; i < K_ * 2 * K_; i += 256) {
            int row = i >> 5, c = i & 31;
            if (row != k) sG[row][c] -= smult[row] * sG[k][c];
        }
        __syncthreads();
    }
    {
        int k = tid >> 4, l = tid & 15;
        sGi[k][l] = sG[k][K_ + l] / sG[k][k];
    }
    __syncthreads();

    // per-row terms
    float term = 0.f;
    if (tid < m) {
        const int i = tid;
        float w[K_], b[K_];
#pragma unroll
        for (int k = 0; k < K_; ++k) w[k] = sW[i][k];
#pragma unroll
        for (int l = 0; l < K_; ++l) {
            float s = 0.f;
#pragma unroll
            for (int k = 0; k < K_; ++k) s += sGi[l][k] * w[k];
            b[l] = s;
        }
        float wb = 0.f, by = 0.f, btb = 0.f;
#pragma unroll
        for (int k = 0; k < K_; ++k) {
            wb += w[k] * b[k];
            by += b[k] * sY[i][k];
            float s = 0.f;
#pragma unroll
            for (int l = 0; l < K_; ++l) s += sT[k][l] * b[l];
            btb += b[k] * s;
        }
        float v = NOISEF * (1.f + wb);
        float Q = sC[i][i] - 2.f * by + btb;
        term = -0.5f * logf(v) - 0.5f * LOG2PI_F - 0.5f * Q / (v * (float)N_);
    }
    if (tid < 64) {
#pragma unroll
        for (int o = 16; o > 0; o >>= 1)
            term += __shfl_xor_sync(0xffffffffu, term, o);
        if ((tid & 31) == 0) sred[tid >> 5] = term;
    }
    __syncthreads();
    if (tid == 0) {
        atomicAdd(&g_loss, (double)(sred[0] + sred[1]) / ((double)P_ * (double)m));
        __threadfence();
        unsigned d = atomicAdd(&g_done, 1u);
        slast = (d == (unsigned)(D_ * P_ - 1)) ? 1 : 0;
    }
    __syncthreads();

    if (slast) {
        // finalize: write output, reset globals for next graph replay
        for (int i = tid; i < D_ * D_; i += 256) g_C[i] = 0.0;
        if (tid == 0) {
            out[0] = -(float)g_loss;
            g_loss = 0.0;
            g_done = 0u;
        }
    }
}

extern "C" void kernel_launch(void* const* d_in, const int* in_sizes, int n_in,
                              void* d_out, int out_size) {
    const float* x     = (const float*)d_in[0];
    const float* W     = (const float*)d_in[1];
    const int*   perms = (const int*)d_in[2];
    (void)in_sizes; (void)n_in; (void)out_size;

    k_xtx<<<NBLK, 256>>>(x);
    k_pairs<<<D_ * P_, 256>>>(W, perms, (float*)d_out);
}

// round 4
// speedup vs baseline: 1.0519x; 1.0519x over previous
#include <cuda_runtime.h>

#define D_      64
#define K_      16
#define N_      65536
#define P_      2
#define NOISEF  0.1f
#define LOG2PI_F 1.83787706640934534f

#define NBLK    296          // 2 CTAs x 148 SMs
#define TROWS   32
#define NTILES  (N_ / TROWS) // 2048

__device__ float    g_Cf[D_ * D_];
__device__ double   g_loss;
__device__ unsigned g_done;

typedef unsigned long long u64;

__device__ __forceinline__ void ffma2(u64& acc, u64 a, u64 b) {
    asm("fma.rn.f32x2 %0, %1, %2, %3;" : "=l"(acc) : "l"(a), "l"(b), "l"(acc));
}
__device__ __forceinline__ u64 dup2(float v) {
    u64 r;
    asm("mov.b64 %0, {%1, %1};" : "=l"(r) : "f"(v));
    return r;
}
__device__ __forceinline__ void cpasync16(unsigned smem, const void* g) {
    asm volatile("cp.async.cg.shared.global [%0], [%1], 16;\n" :: "r"(smem), "l"(g));
}
__device__ __forceinline__ void cp_commit() {
    asm volatile("cp.async.commit_group;\n" ::: "memory");
}
__device__ __forceinline__ void cp_wait1() {
    asm volatile("cp.async.wait_group 1;\n" ::: "memory");
}

// ---------------------------------------------------------------------------
// Kernel 1: C = x^T x. 296 persistent blocks, 3-stage cp.async rotation,
// one barrier per 32-row tile. Float atomics into g_Cf.
// ---------------------------------------------------------------------------
__global__ __launch_bounds__(256, 2) void k_xtx(const float* __restrict__ x) {
    __shared__ __align__(16) float sx[3][TROWS * 64];

    const int tid = threadIdx.x;
    const int g   = tid >> 6;
    const int t   = tid & 63;
    const int ti  = (t >> 3) << 3;
    const int tj  = (t & 7) << 3;

    u64 acc2[8][4];
#pragma unroll
    for (int u = 0; u < 8; ++u)
#pragma unroll
        for (int v = 0; v < 4; ++v) acc2[u][v] = 0ull;

    unsigned sb[3];
#pragma unroll
    for (int s = 0; s < 3; ++s)
        sb[s] = (unsigned)__cvta_generic_to_shared(&sx[s][0]);

    // prologue: prefetch tiles bid, bid+NBLK into slots 0, 1
    {
        const float4* g4 = reinterpret_cast<const float4*>(x + (long long)blockIdx.x * TROWS * 64);
        cpasync16(sb[0] + tid * 16, g4 + tid);
        cpasync16(sb[0] + (tid + 256) * 16, g4 + tid + 256);
        cp_commit();
        int t1 = blockIdx.x + NBLK;
        if (t1 < NTILES) {
            const float4* h4 = reinterpret_cast<const float4*>(x + (long long)t1 * TROWS * 64);
            cpasync16(sb[1] + tid * 16, h4 + tid);
            cpasync16(sb[1] + (tid + 256) * 16, h4 + tid + 256);
        }
        cp_commit();
    }

    int sidx = 0;
    for (int tile = blockIdx.x; tile < NTILES; tile += NBLK) {
        cp_wait1();               // this tile's copies done (1 newer group pending)
        __syncthreads();          // all threads past previous compute + copies visible

        // prefetch tile+2*NBLK into the slot freed last iteration
        int nn = tile + 2 * NBLK;
        if (nn < NTILES) {
            int s2 = sidx + 2; if (s2 >= 3) s2 -= 3;
            const float4* g4 = reinterpret_cast<const float4*>(x + (long long)nn * TROWS * 64);
            cpasync16(sb[s2] + tid * 16, g4 + tid);
            cpasync16(sb[s2] + (tid + 256) * 16, g4 + tid + 256);
        }
        cp_commit();

        const float* rb = &sx[sidx][0] + g * (8 * 64);
#pragma unroll
        for (int rr = 0; rr < 8; ++rr) {
            const float4* xiv = reinterpret_cast<const float4*>(rb + rr * 64 + ti);
            float4 a0 = xiv[0], a1 = xiv[1];
            u64 xi2[8];
            xi2[0] = dup2(a0.x); xi2[1] = dup2(a0.y);
            xi2[2] = dup2(a0.z); xi2[3] = dup2(a0.w);
            xi2[4] = dup2(a1.x); xi2[5] = dup2(a1.y);
            xi2[6] = dup2(a1.z); xi2[7] = dup2(a1.w);
            const u64* xjv = reinterpret_cast<const u64*>(rb + rr * 64 + tj);
            u64 xj2[4];
#pragma unroll
            for (int v = 0; v < 4; ++v) xj2[v] = xjv[v];
#pragma unroll
            for (int u = 0; u < 8; ++u)
#pragma unroll
                for (int v = 0; v < 4; ++v) ffma2(acc2[u][v], xi2[u], xj2[v]);
        }
        sidx += 1; if (sidx >= 3) sidx -= 3;
    }
    __syncthreads();

    // reduce the 4 groups into sx[0..1] (4096 floats), then float atomics
    float* red = &sx[0][0];
    for (int gg = 0; gg < 4; ++gg) {
        if (g == gg) {
#pragma unroll
            for (int u = 0; u < 8; ++u)
#pragma unroll
                for (int v = 0; v < 4; ++v) {
                    float lo = __uint_as_float((unsigned)(acc2[u][v] & 0xffffffffull));
                    float hi = __uint_as_float((unsigned)(acc2[u][v] >> 32));
                    int idx = (ti + u) * 64 + tj + 2 * v;
                    if (gg == 0) { red[idx] = lo; red[idx + 1] = hi; }
                    else         { red[idx] += lo; red[idx + 1] += hi; }
                }
        }
        __syncthreads();
    }
#pragma unroll
    for (int i = 0; i < 16; ++i)
        atomicAdd(&g_Cf[tid + 256 * i], red[tid + 256 * i]);
}

// ---------------------------------------------------------------------------
// Kernel 2: one block per (a,p). Woodbury, latency-lean:
//   G = 0.1 I + sum_{i>=m} w_i w_i^T   (masked full-unroll loops)
//   Ginv via warp-0 shuffle Jordan (no block barriers), overlapped with
//   Y[i] = sum_{j>=m} Craw[perm_i, perm_j] w_j   on warps 1-7
//   T = sum_{i>=m} w_i (x) Y_i
//   b = Ginv w ; v = 0.1(1+w.b) ; Q = C_ii - 2 b.Y + b^T T b
// ---------------------------------------------------------------------------
__global__ __launch_bounds__(256) void k_pairs(const float* __restrict__ W,
                                               const int* __restrict__ perms,
                                               float* __restrict__ out) {
    __shared__ __align__(16) float sCraw[D_ * D_];
    __shared__ __align__(16) float sW[D_ * K_];
    __shared__ __align__(16) float sY[D_ * K_];
    __shared__ __align__(16) float sT[K_ * K_];
    __shared__ __align__(16) float sG[K_ * K_];
    __shared__ __align__(16) float sGi[K_ * K_];
    __shared__ int   sperm[D_];
    __shared__ float sred[2];
    __shared__ int   slast;

    const int tid = threadIdx.x;
    const int a   = blockIdx.x >> 1;
    const int m   = a + 1;
    const int* perm = perms + (a * P_ + (blockIdx.x & 1)) * D_;

    if (tid < D_) sperm[tid] = perm[tid];
#pragma unroll
    for (int i = 0; i < 16; ++i)
        sCraw[tid + 256 * i] = g_Cf[tid + 256 * i];
#pragma unroll
    for (int i = 0; i < 4; ++i) {
        int idx = tid + 256 * i;
        sW[idx] = W[perm[idx >> 4] * K_ + (idx & 15)];
    }
    __syncthreads();

    // G: one element per thread, masked full-unroll loop
    const int gk = tid >> 4, gl = tid & 15;
    {
        float s = (gk == gl) ? NOISEF : 0.f;
#pragma unroll
        for (int i = 0; i < D_; ++i) {
            float w1 = sW[i * K_ + gk], w2 = sW[i * K_ + gl];
            if (i >= m) s += w1 * w2;
        }
        sG[gk * K_ + gl] = s;
    }
    __syncthreads();

    if (tid < 32) {
        // warp 0: shuffle Jordan inversion of G (lanes 0-15: G columns,
        // lanes 16-31: identity columns)
        const int lane = tid;
        float col[K_];
#pragma unroll
        for (int r = 0; r < K_; ++r)
            col[r] = (lane < K_) ? sG[r * K_ + lane]
                                 : ((r == lane - K_) ? 1.f : 0.f);
#pragma unroll
        for (int k = 0; k < K_; ++k) {
            float pv = __shfl_sync(0xffffffffu, col[k], k);
            float ip = 1.0f / pv;
            float ck = col[k];
#pragma unroll
            for (int r = 0; r < K_; ++r) {
                if (r != k) {
                    float mr = __shfl_sync(0xffffffffu, col[r], k) * ip;
                    col[r] -= mr * ck;
                }
            }
        }
        float own = 1.f;
#pragma unroll
        for (int r = 0; r < K_; ++r)
            if (r == lane) own = col[r];
        float oinv = 1.0f / own;
#pragma unroll
        for (int r = 0; r < K_; ++r) {
            float di = __shfl_sync(0xffffffffu, oinv, r);
            if (lane >= K_) sGi[r * K_ + (lane - K_)] = col[r] * di;
        }
    } else {
        // warps 1-7: Y (256 items over 224 threads)
        const int t = tid - 32;
        for (int it = t; it < 256; it += 224) {
            const int i  = it & 63;
            const int kb = (it >> 6) << 2;
            const int pi = sperm[i] * D_;
            float y0 = 0.f, y1 = 0.f, y2 = 0.f, y3 = 0.f;
#pragma unroll
            for (int j = 0; j < D_; ++j) {
                float c = sCraw[pi + sperm[j]];
                const float4 wv = *reinterpret_cast<const float4*>(sW + j * K_ + kb);
                if (j >= m) {
                    y0 += c * wv.x;
                    y1 += c * wv.y;
                    y2 += c * wv.z;
                    y3 += c * wv.w;
                }
            }
            *reinterpret_cast<float4*>(sY + i * K_ + kb) = make_float4(y0, y1, y2, y3);
        }
    }
    __syncthreads();

    // T: one element per thread
    {
        float s = 0.f;
#pragma unroll
        for (int i = 0; i < D_; ++i) {
            float wv = sW[i * K_ + gk], yv = sY[i * K_ + gl];
            if (i >= m) s += wv * yv;
        }
        sT[gk * K_ + gl] = s;
    }
    __syncthreads();

    // per-row terms
    float term = 0.f;
    if (tid < m) {
        const int i = tid;
        float w[K_], b[K_];
#pragma unroll
        for (int k4 = 0; k4 < K_; k4 += 4) {
            const float4 wv = *reinterpret_cast<const float4*>(sW + i * K_ + k4);
            w[k4] = wv.x; w[k4 + 1] = wv.y; w[k4 + 2] = wv.z; w[k4 + 3] = wv.w;
        }
#pragma unroll
        for (int l = 0; l < K_; ++l) {
            float s = 0.f;
#pragma unroll
            for (int k = 0; k < K_; ++k) s += sGi[l * K_ + k] * w[k];
            b[l] = s;
        }
        float wb = 0.f, by = 0.f, btb = 0.f;
#pragma unroll
        for (int k = 0; k < K_; ++k) {
            wb += w[k] * b[k];
            by += b[k] * sY[i * K_ + k];
            float s = 0.f;
#pragma unroll
            for (int l = 0; l < K_; ++l) s += sT[k * K_ + l] * b[l];
            btb += b[k] * s;
        }
        const int pi = sperm[i];
        float v = NOISEF * (1.f + wb);
        float Q = sCraw[pi * 65] - 2.f * by + btb;
        term = -0.5f * logf(v) - 0.5f * LOG2PI_F - 0.5f * Q / (v * (float)N_);
    }
    if (tid < 64) {
#pragma unroll
        for (int o = 16; o > 0; o >>= 1)
            term += __shfl_xor_sync(0xffffffffu, term, o);
        if ((tid & 31) == 0) sred[tid >> 5] = term;
    }
    __syncthreads();
    if (tid == 0) {
        atomicAdd(&g_loss, (double)(sred[0] + sred[1]) / ((double)P_ * (double)m));
        __threadfence();
        unsigned d = atomicAdd(&g_done, 1u);
        slast = (d == (unsigned)(D_ * P_ - 1)) ? 1 : 0;
    }
    __syncthreads();

    if (slast) {
        for (int i = tid; i < D_ * D_; i += 256) g_Cf[i] = 0.f;
        if (tid == 0) {
            out[0] = -(float)g_loss;
            g_loss = 0.0;
            g_done = 0u;
        }
    }
}

extern "C" void kernel_launch(void* const* d_in, const int* in_sizes, int n_in,
                              void* d_out, int out_size) {
    const float* x     = (const float*)d_in[0];
    const float* W     = (const float*)d_in[1];
    const int*   perms = (const int*)d_in[2];
    (void)in_sizes; (void)n_in; (void)out_size;

    k_xtx<<<NBLK, 256>>>(x);
    k_pairs<<<D_ * P_, 256>>>(W, perms, (float*)d_out);
}